// round 5
// baseline (speedup 1.0000x reference)
#include <cuda_runtime.h>
#include <cstdint>

// ---------------- problem constants ----------------
#define NPC       8000          // 64000/8 render points
#define NPC_PAD   8192
#define NREF      10000         // 80000/8 ref points
#define TM        250           // refs per chunk (phase A sweep length)
#define GRID_REF  40            // 40 * 250 = 10000
#define PCTILE    1024          // pc per block (phase B sweep length)
#define GRID_PC   8             // 8 * 1024 = 8192
#define NBLOCKS   (GRID_REF * GRID_PC)   // 320
#define NT        128
#define REFPAIRS_ALLOC 5504     // covers refBase/2 + 511 for last chunk

typedef unsigned long long ull;

// ---------------- device scratch (no cudaMalloc allowed) ----------------
__device__ ull      g_pcAx[NPC_PAD / 2];     // {-2*p_{2i}x, -2*p_{2i+1}x}
__device__ ull      g_pcAy[NPC_PAD / 2];
__device__ ull      g_pcPk[NPC_PAD * 4];     // per pc: {x,x},{y,y},{s,s},pad
__device__ ull      g_refPk[NREF * 4];       // per ref: {x,x},{y,y},{s,s},pad
__device__ ull      g_refBx[REFPAIRS_ALLOC]; // {-2*r_{2j}x, -2*r_{2j+1}x}
__device__ ull      g_refBy[REFPAIRS_ALLOC];
__device__ float    g_pcn[NPC_PAD];          // |p|^2
__device__ float    g_refn[NREF];            // |r|^2
__device__ unsigned g_min1[NPC_PAD];         // transformed-key min of (|r|^2 - 2 p.r)
__device__ unsigned g_min2[NREF];            // transformed-key min of (|p|^2 - 2 p.r)
__device__ unsigned g_done;

// ---------------- packed f32x2 helpers ----------------
static __device__ __forceinline__ ull pk2(float lo, float hi) {
    ull r; asm("mov.b64 %0, {%1, %2};" : "=l"(r) : "f"(lo), "f"(hi)); return r;
}
static __device__ __forceinline__ void upk2(ull v, float& lo, float& hi) {
    asm("mov.b64 {%0, %1}, %2;" : "=f"(lo), "=f"(hi) : "l"(v));
}
static __device__ __forceinline__ ull vfma2(ull a, ull b, ull c) {
    ull r; asm("fma.rn.f32x2 %0, %1, %2, %3;" : "=l"(r) : "l"(a), "l"(b), "l"(c)); return r;
}

// monotone float -> uint key (handles negatives) for atomicMin
static __device__ __forceinline__ unsigned enc(float f) {
    unsigned u = __float_as_uint(f);
    return u ^ (((unsigned)((int)u >> 31)) | 0x80000000u);
}
static __device__ __forceinline__ float dec(unsigned k) {
    unsigned b = (k & 0x80000000u) ? (k ^ 0x80000000u) : ~k;
    return __uint_as_float(b);
}

// ---------------------------------------------------------------------------
// K1: gather subsampled points (fp32 linspace trunc semantics), prepack all
//     operand forms, init min arrays + done counter.
// ---------------------------------------------------------------------------
__global__ void k_init(const float* __restrict__ in0, const float* __restrict__ in1) {
    int i2 = blockIdx.x * 256 + threadIdx.x;
    const float D1 = 63999.0f / 7999.0f;   // fp32 rn compile-time
    const float D2 = 79999.0f / 9999.0f;

    if (i2 < NPC_PAD / 2) {
        float x[2], y[2];
#pragma unroll
        for (int k = 0; k < 2; k++) {
            int i = 2 * i2 + k;
            if (i < NPC) {
                int si = (int)((float)i * D1);
                x[k] = in0[2 * si]; y[k] = in0[2 * si + 1];
            } else {
                x[k] = 1e9f; y[k] = 1e9f;   // pad: huge -> never wins any min
            }
            float s = x[k] * x[k] + y[k] * y[k];
            g_pcPk[4 * i + 0] = pk2(x[k], x[k]);
            g_pcPk[4 * i + 1] = pk2(y[k], y[k]);
            g_pcPk[4 * i + 2] = pk2(s, s);
            g_pcPk[4 * i + 3] = 0ull;
            g_pcn[i]  = s;
            g_min1[i] = 0xFFFFFFFFu;
        }
        g_pcAx[i2] = pk2(-2.0f * x[0], -2.0f * x[1]);
        g_pcAy[i2] = pk2(-2.0f * y[0], -2.0f * y[1]);
    }
    if (i2 < REFPAIRS_ALLOC) {
        float x[2] = {0.0f, 0.0f}, y[2] = {0.0f, 0.0f};
#pragma unroll
        for (int k = 0; k < 2; k++) {
            int j = 2 * i2 + k;
            if (j < NREF) {
                int sj = (int)((float)j * D2);
                x[k] = in1[2 * sj]; y[k] = in1[2 * sj + 1];
                float s = x[k] * x[k] + y[k] * y[k];
                g_refPk[4 * j + 0] = pk2(x[k], x[k]);
                g_refPk[4 * j + 1] = pk2(y[k], y[k]);
                g_refPk[4 * j + 2] = pk2(s, s);
                g_refPk[4 * j + 3] = 0ull;
                g_refn[j]  = s;
                g_min2[j] = 0xFFFFFFFFu;
            }
        }
        // pad ref pairs -> zeros: m = |p|^2 >= 0, finite, atomics guarded out
        g_refBx[i2] = pk2(-2.0f * x[0], -2.0f * x[1]);
        g_refBy[i2] = pk2(-2.0f * y[0], -2.0f * y[1]);
    }
    if (i2 == 0) g_done = 0u;
}

// ---------------------------------------------------------------------------
// K2: main. Block (cx,cy) covers pc tile [cy*1024, +1024) x ref chunk [cx*250, +250).
//  Phase A: thread owns 8 pc (packed -2p), sweeps 250 refs from shared
//           ({x,x},{y,y},{s,s} prepacked) -> min of (|r|^2 - 2 p.r) per pc.
//  Phase B: thread owns 8 refs (packed -2r), sweeps 1024 pc from shared
//           -> min of (|p|^2 - 2 p.r) per ref.
//  Last block (ticket) reduces: d = sqrt(max(min + |own|^2, 0)), means, out.
// ---------------------------------------------------------------------------
__global__ void __launch_bounds__(NT) k_main(float* __restrict__ out) {
    __shared__ __align__(16) ull sh[PCTILE * 4];   // 32KB, reused both phases
    __shared__ float sred[8];
    __shared__ int   sflag;

    int b = blockIdx.x, t = threadIdx.x;
    int cx = b % GRID_REF, cy = b / GRID_REF;
    int refBase = cx * TM;
    int pcBase  = cy * PCTILE;

    // ---- Phase A: fill ref chunk (250 entries * 32B) ----
    {
        const ulonglong2* src = (const ulonglong2*)(g_refPk + (size_t)refBase * 4);
        ulonglong2* dst = (ulonglong2*)sh;
        for (int k = t; k < TM * 2; k += NT) dst[k] = src[k];
    }
    __syncthreads();

    {
        int pp = pcBase / 2 + t * 4;
        ull ax0 = g_pcAx[pp + 0], ax1 = g_pcAx[pp + 1], ax2 = g_pcAx[pp + 2], ax3 = g_pcAx[pp + 3];
        ull ay0 = g_pcAy[pp + 0], ay1 = g_pcAy[pp + 1], ay2 = g_pcAy[pp + 2], ay3 = g_pcAy[pp + 3];
        float m0 = 3.4e38f, m1 = 3.4e38f, m2 = 3.4e38f, m3 = 3.4e38f;
        float m4 = 3.4e38f, m5 = 3.4e38f, m6 = 3.4e38f, m7 = 3.4e38f;

#pragma unroll 5
        for (int j = 0; j < TM; j++) {
            ulonglong2 v = *((const ulonglong2*)&sh[4 * j]);   // {x,x},{y,y}
            ull ss = sh[4 * j + 2];                            // {s,s}
            ull q0 = vfma2(ax0, v.x, vfma2(ay0, v.y, ss));
            ull q1 = vfma2(ax1, v.x, vfma2(ay1, v.y, ss));
            ull q2 = vfma2(ax2, v.x, vfma2(ay2, v.y, ss));
            ull q3 = vfma2(ax3, v.x, vfma2(ay3, v.y, ss));
            float f0, f1, f2, f3, f4, f5, f6, f7;
            upk2(q0, f0, f1); upk2(q1, f2, f3);
            upk2(q2, f4, f5); upk2(q3, f6, f7);
            m0 = fminf(m0, f0); m1 = fminf(m1, f1);
            m2 = fminf(m2, f2); m3 = fminf(m3, f3);
            m4 = fminf(m4, f4); m5 = fminf(m5, f5);
            m6 = fminf(m6, f6); m7 = fminf(m7, f7);
        }
        int myPc = pcBase + t * 8;
        atomicMin(&g_min1[myPc + 0], enc(m0));
        atomicMin(&g_min1[myPc + 1], enc(m1));
        atomicMin(&g_min1[myPc + 2], enc(m2));
        atomicMin(&g_min1[myPc + 3], enc(m3));
        atomicMin(&g_min1[myPc + 4], enc(m4));
        atomicMin(&g_min1[myPc + 5], enc(m5));
        atomicMin(&g_min1[myPc + 6], enc(m6));
        atomicMin(&g_min1[myPc + 7], enc(m7));
    }
    __syncthreads();

    // ---- Phase B: fill pc tile (1024 entries * 32B) ----
    {
        const ulonglong2* src = (const ulonglong2*)(g_pcPk + (size_t)pcBase * 4);
        ulonglong2* dst = (ulonglong2*)sh;
        for (int k = t; k < PCTILE * 2; k += NT) dst[k] = src[k];
    }
    __syncthreads();

    {
        int rp = refBase / 2 + t * 4;
        ull bx0 = g_refBx[rp + 0], bx1 = g_refBx[rp + 1], bx2 = g_refBx[rp + 2], bx3 = g_refBx[rp + 3];
        ull by0 = g_refBy[rp + 0], by1 = g_refBy[rp + 1], by2 = g_refBy[rp + 2], by3 = g_refBy[rp + 3];
        float m0 = 3.4e38f, m1 = 3.4e38f, m2 = 3.4e38f, m3 = 3.4e38f;
        float m4 = 3.4e38f, m5 = 3.4e38f, m6 = 3.4e38f, m7 = 3.4e38f;

#pragma unroll 4
        for (int i = 0; i < PCTILE; i++) {
            ulonglong2 v = *((const ulonglong2*)&sh[4 * i]);
            ull ss = sh[4 * i + 2];
            ull q0 = vfma2(bx0, v.x, vfma2(by0, v.y, ss));
            ull q1 = vfma2(bx1, v.x, vfma2(by1, v.y, ss));
            ull q2 = vfma2(bx2, v.x, vfma2(by2, v.y, ss));
            ull q3 = vfma2(bx3, v.x, vfma2(by3, v.y, ss));
            float f0, f1, f2, f3, f4, f5, f6, f7;
            upk2(q0, f0, f1); upk2(q1, f2, f3);
            upk2(q2, f4, f5); upk2(q3, f6, f7);
            m0 = fminf(m0, f0); m1 = fminf(m1, f1);
            m2 = fminf(m2, f2); m3 = fminf(m3, f3);
            m4 = fminf(m4, f4); m5 = fminf(m5, f5);
            m6 = fminf(m6, f6); m7 = fminf(m7, f7);
        }
        int rl = t * 8;
        float mm[8] = {m0, m1, m2, m3, m4, m5, m6, m7};
#pragma unroll
        for (int k = 0; k < 8; k++)
            if (rl + k < TM) atomicMin(&g_min2[refBase + rl + k], enc(mm[k]));
    }

    // ---- last-block tail reduction ----
    __threadfence();
    __syncthreads();
    if (t == 0) sflag = (atomicAdd(&g_done, 1u) == (unsigned)(NBLOCKS - 1));
    __syncthreads();
    if (!sflag) return;
    __threadfence();

    float s1 = 0.0f, s2 = 0.0f;
    for (int i = t; i < NPC; i += NT) {
        float v = dec(__ldcg(&g_min1[i])) + g_pcn[i];
        s1 += sqrtf(fmaxf(v, 0.0f));
    }
    for (int j = t; j < NREF; j += NT) {
        float v = dec(__ldcg(&g_min2[j])) + g_refn[j];
        s2 += sqrtf(fmaxf(v, 0.0f));
    }
#pragma unroll
    for (int off = 16; off > 0; off >>= 1) {
        s1 += __shfl_down_sync(0xFFFFFFFFu, s1, off);
        s2 += __shfl_down_sync(0xFFFFFFFFu, s2, off);
    }
    int w = t >> 5;
    if ((t & 31) == 0) { sred[2 * w] = s1; sred[2 * w + 1] = s2; }
    __syncthreads();
    if (t == 0) {
        float S1 = sred[0] + sred[2] + sred[4] + sred[6];
        float S2 = sred[1] + sred[3] + sred[5] + sred[7];
        out[0] = (S1 * (1.0f / NPC) + S2 * (1.0f / NREF)) * 0.5f;
    }
}

extern "C" void kernel_launch(void* const* d_in, const int* in_sizes, int n_in,
                              void* d_out, int out_size) {
    const float* in0 = (const float*)d_in[0];   // img_render_points
    const float* in1 = (const float*)d_in[1];   // ref point cloud
    float* out = (float*)d_out;

    k_init<<<22, 256>>>(in0, in1);
    k_main<<<NBLOCKS, NT>>>(out);
}

// round 6
// speedup vs baseline: 1.8662x; 1.8662x over previous
#include <cuda_runtime.h>
#include <cstdint>

// ---------------- problem constants ----------------
#define NPC       8000          // 64000/8 render points
#define NPC_PAD   8192
#define NREF      10000         // 80000/8 ref points
#define NREF_PAD  10240
#define PCPAIRS   (NPC_PAD / 2)    // 4096
#define REFPAIRS  (NREF_PAD / 2)   // 5120
#define TIL       256           // points per tile (both dims)
#define TILP      (TIL / 2)     // 128 packed pairs per tile
#define GRID_PC   (NPC_PAD / TIL)   // 32
#define GRID_REF  (NREF_PAD / TIL)  // 40
#define NBLOCKS   (GRID_PC * GRID_REF)   // 1280
#define NT        128
#define PAD_S     1e30f

typedef unsigned long long ull;

// ---------------- device scratch (no cudaMalloc allowed) ----------------
// Swept-pair packs, 4 ull per pair (32B, 16B-aligned): {x0,x1},{y0,y1},{s0,s1},pad
__device__ __align__(16) ull g_pcPair[PCPAIRS * 4];
__device__ __align__(16) ull g_refPair[REFPAIRS * 4];
__device__ float2   g_pcXY[NPC_PAD];
__device__ float2   g_refXY[NREF_PAD];
__device__ unsigned g_min1[NPC_PAD];    // key-min of (|r|^2 - 2 p.r) per pc
__device__ unsigned g_min2[NREF_PAD];   // key-min of (|p|^2 - 2 p.r) per ref
__device__ unsigned g_done;

// ---------------- packed f32x2 helpers ----------------
static __device__ __forceinline__ ull pk2(float lo, float hi) {
    ull r; asm("mov.b64 %0, {%1, %2};" : "=l"(r) : "f"(lo), "f"(hi)); return r;
}
static __device__ __forceinline__ void upk2(ull v, float& lo, float& hi) {
    asm("mov.b64 {%0, %1}, %2;" : "=f"(lo), "=f"(hi) : "l"(v));
}
static __device__ __forceinline__ ull vfma2(ull a, ull b, ull c) {
    ull r; asm("fma.rn.f32x2 %0, %1, %2, %3;" : "=l"(r) : "l"(a), "l"(b), "l"(c)); return r;
}

// monotone float <-> uint key (handles negatives) for atomicMin
static __device__ __forceinline__ unsigned enc(float f) {
    unsigned u = __float_as_uint(f);
    return u ^ (((unsigned)((int)u >> 31)) | 0x80000000u);
}
static __device__ __forceinline__ float dec(unsigned k) {
    unsigned b = (k & 0x80000000u) ? (k ^ 0x80000000u) : ~k;
    return __uint_as_float(b);
}

// ---------------------------------------------------------------------------
// K1: gather subsampled points (fp32 linspace trunc semantics), build packed
//     pair arrays + scalar arrays, init min arrays + done counter.
//     Pad slots: x=y=0, s=1e30 -> never win a sweep min; pad owned slots
//     atomically write into pad min entries which the reduce skips.
// ---------------------------------------------------------------------------
__global__ void k_init(const float* __restrict__ in0, const float* __restrict__ in1) {
    int i = blockIdx.x * 256 + threadIdx.x;   // pair index
    const float D1 = 63999.0f / 7999.0f;      // fp32 rn, compile time
    const float D2 = 79999.0f / 9999.0f;

    if (i < PCPAIRS) {
        float x[2], y[2], s[2];
#pragma unroll
        for (int k = 0; k < 2; k++) {
            int p = 2 * i + k;
            if (p < NPC) {
                int sp = (int)((float)p * D1);
                x[k] = in0[2 * sp]; y[k] = in0[2 * sp + 1];
                s[k] = x[k] * x[k] + y[k] * y[k];
            } else { x[k] = 0.0f; y[k] = 0.0f; s[k] = PAD_S; }
            g_pcXY[p] = make_float2(x[k], y[k]);
            g_min1[p] = 0xFFFFFFFFu;
        }
        g_pcPair[4 * i + 0] = pk2(x[0], x[1]);
        g_pcPair[4 * i + 1] = pk2(y[0], y[1]);
        g_pcPair[4 * i + 2] = pk2(s[0], s[1]);
        g_pcPair[4 * i + 3] = 0ull;
    }
    if (i < REFPAIRS) {
        float x[2], y[2], s[2];
#pragma unroll
        for (int k = 0; k < 2; k++) {
            int p = 2 * i + k;
            if (p < NREF) {
                int sp = (int)((float)p * D2);
                x[k] = in1[2 * sp]; y[k] = in1[2 * sp + 1];
                s[k] = x[k] * x[k] + y[k] * y[k];
            } else { x[k] = 0.0f; y[k] = 0.0f; s[k] = PAD_S; }
            g_refXY[p] = make_float2(x[k], y[k]);
            g_min2[p] = 0xFFFFFFFFu;
        }
        g_refPair[4 * i + 0] = pk2(x[0], x[1]);
        g_refPair[4 * i + 1] = pk2(y[0], y[1]);
        g_refPair[4 * i + 2] = pk2(s[0], s[1]);
        g_refPair[4 * i + 3] = 0ull;
    }
    if (i == 0) g_done = 0u;
}

// ---------------------------------------------------------------------------
// K2: main. Block (cx,cy): pc tile [cy*256,+256) x ref tile [cx*256,+256).
//  Both tiles loaded to shared up front (one sync total).
//  Phase A: thread owns pc points (base+t, base+128+t) hoisted as {-2px,-2px}
//           packs; sweeps 128 packed ref pairs -> min of (|r|^2 - 2 p.r).
//  Phase B: symmetric, owns 2 refs, sweeps 128 packed pc pairs.
//  Last block (ticket) reduces: d = sqrt(max(min + |own|^2, 0)), means, out.
// ---------------------------------------------------------------------------
__global__ void __launch_bounds__(NT, 10) k_main(float* __restrict__ out) {
    __shared__ __align__(16) ull shR[TILP * 4];   // 4KB ref tile
    __shared__ __align__(16) ull shP[TILP * 4];   // 4KB pc tile
    __shared__ float sred[8];
    __shared__ int   sflag;

    int b = blockIdx.x, t = threadIdx.x;
    int cx = b % GRID_REF, cy = b / GRID_REF;
    int refBase = cx * TIL;     // point index
    int pcBase  = cy * TIL;

    // ---- load both swept tiles (256 x LDG.128 each tile) ----
    {
        const ulonglong2* srcR = (const ulonglong2*)(g_refPair + (size_t)(cx * TILP) * 4);
        const ulonglong2* srcP = (const ulonglong2*)(g_pcPair  + (size_t)(cy * TILP) * 4);
        ulonglong2* dstR = (ulonglong2*)shR;
        ulonglong2* dstP = (ulonglong2*)shP;
#pragma unroll
        for (int k = t; k < TILP * 2; k += NT) { dstR[k] = srcR[k]; dstP[k] = srcP[k]; }
    }
    __syncthreads();

    // ---- Phase A: min over refs for owned pc (pcBase+t, pcBase+128+t) ----
    {
        float2 p0 = g_pcXY[pcBase + t];
        float2 p1 = g_pcXY[pcBase + NT + t];
        ull pX0 = pk2(-2.0f * p0.x, -2.0f * p0.x);
        ull pY0 = pk2(-2.0f * p0.y, -2.0f * p0.y);
        ull pX1 = pk2(-2.0f * p1.x, -2.0f * p1.x);
        ull pY1 = pk2(-2.0f * p1.y, -2.0f * p1.y);
        float m00 = PAD_S, m01 = PAD_S, m10 = PAD_S, m11 = PAD_S;

#pragma unroll 8
        for (int j = 0; j < TILP; j++) {
            ulonglong2 v = *((const ulonglong2*)&shR[4 * j]);   // {x0,x1},{y0,y1}
            ull S = shR[4 * j + 2];                             // {s0,s1}
            ull q0 = vfma2(pX0, v.x, vfma2(pY0, v.y, S));
            ull q1 = vfma2(pX1, v.x, vfma2(pY1, v.y, S));
            float a, bb, c, d;
            upk2(q0, a, bb); upk2(q1, c, d);
            m00 = fminf(m00, a); m01 = fminf(m01, bb);
            m10 = fminf(m10, c); m11 = fminf(m11, d);
        }
        atomicMin(&g_min1[pcBase + t],      enc(fminf(m00, m01)));
        atomicMin(&g_min1[pcBase + NT + t], enc(fminf(m10, m11)));
    }

    // ---- Phase B: min over pc for owned refs (refBase+t, refBase+128+t) ----
    {
        float2 r0 = g_refXY[refBase + t];
        float2 r1 = g_refXY[refBase + NT + t];
        ull rX0 = pk2(-2.0f * r0.x, -2.0f * r0.x);
        ull rY0 = pk2(-2.0f * r0.y, -2.0f * r0.y);
        ull rX1 = pk2(-2.0f * r1.x, -2.0f * r1.x);
        ull rY1 = pk2(-2.0f * r1.y, -2.0f * r1.y);
        float m00 = PAD_S, m01 = PAD_S, m10 = PAD_S, m11 = PAD_S;

#pragma unroll 8
        for (int j = 0; j < TILP; j++) {
            ulonglong2 v = *((const ulonglong2*)&shP[4 * j]);
            ull S = shP[4 * j + 2];
            ull q0 = vfma2(rX0, v.x, vfma2(rY0, v.y, S));
            ull q1 = vfma2(rX1, v.x, vfma2(rY1, v.y, S));
            float a, bb, c, d;
            upk2(q0, a, bb); upk2(q1, c, d);
            m00 = fminf(m00, a); m01 = fminf(m01, bb);
            m10 = fminf(m10, c); m11 = fminf(m11, d);
        }
        atomicMin(&g_min2[refBase + t],      enc(fminf(m00, m01)));
        atomicMin(&g_min2[refBase + NT + t], enc(fminf(m10, m11)));
    }

    // ---- last-block tail reduction ----
    __threadfence();
    __syncthreads();
    if (t == 0) sflag = (atomicAdd(&g_done, 1u) == (unsigned)(NBLOCKS - 1));
    __syncthreads();
    if (!sflag) return;
    __threadfence();

    float s1 = 0.0f, s2 = 0.0f;
    for (int i = t; i < NPC; i += NT) {
        float2 p = g_pcXY[i];
        float v = dec(__ldcg(&g_min1[i])) + (p.x * p.x + p.y * p.y);
        s1 += sqrtf(fmaxf(v, 0.0f));
    }
    for (int j = t; j < NREF; j += NT) {
        float2 r = g_refXY[j];
        float v = dec(__ldcg(&g_min2[j])) + (r.x * r.x + r.y * r.y);
        s2 += sqrtf(fmaxf(v, 0.0f));
    }
#pragma unroll
    for (int off = 16; off > 0; off >>= 1) {
        s1 += __shfl_down_sync(0xFFFFFFFFu, s1, off);
        s2 += __shfl_down_sync(0xFFFFFFFFu, s2, off);
    }
    int w = t >> 5;
    if ((t & 31) == 0) { sred[2 * w] = s1; sred[2 * w + 1] = s2; }
    __syncthreads();
    if (t == 0) {
        float S1 = sred[0] + sred[2] + sred[4] + sred[6];
        float S2 = sred[1] + sred[3] + sred[5] + sred[7];
        out[0] = (S1 * (1.0f / NPC) + S2 * (1.0f / NREF)) * 0.5f;
    }
}

extern "C" void kernel_launch(void* const* d_in, const int* in_sizes, int n_in,
                              void* d_out, int out_size) {
    const float* in0 = (const float*)d_in[0];   // img_render_points
    const float* in1 = (const float*)d_in[1];   // ref point cloud
    float* out = (float*)d_out;

    k_init<<<20, 256>>>(in0, in1);
    k_main<<<NBLOCKS, NT>>>(out);
}